// round 1
// baseline (speedup 1.0000x reference)
#include <cuda_runtime.h>
#include <math.h>

// Problem constants
#define NN 1024          // nodes
#define BB 64            // batch
#define NB (NN*BB)       // 65536 rows in (N,B,*) layout
#define HH 128           // hidden
#define F0 130           // layer0 concat features (I + H)
#define F0P 136          // padded to multiple of 8
#define F1P 256          // layer1 concat features (H + H)
#define BF0 (BB*F0P)     // 8704  (= 68*128)
#define BF1 (BB*F1P)     // 16384 (= 128*128)

// ---------------- static device scratch (no allocation allowed) ----------------
__device__ float g_G[(size_t)4096*1024];        // [A0; 2A0^2; A1; 2A1^2]
__device__ float g_x[(size_t)NB*256];           // concat input, stride F0P or F1P
__device__ float g_y[(size_t)4*1024*BF1];       // G @ x  (4 slices of (N,B,F))
__device__ float g_gate[(size_t)NB*256];        // sigmoid gates: r=[0:128), u=[128:256)
__device__ float g_s0[(size_t)NB*HH];
__device__ float g_s1[(size_t)NB*HH];
__device__ float g_Wg0[5*F0P*256];
__device__ float g_Wc0[5*F0P*128];
__device__ float g_Wg1[5*F1P*256];
__device__ float g_Wc1[5*F1P*128];

// ---------------- SGEMM: C(M,Ncols) = alpha * A(M,K) @ B(K,Ncols) ----------------
// 128x128 block, BK=8, 256 threads, 8x8 per-thread tile, double-buffered smem.
__global__ __launch_bounds__(256)
void sgemm_graph_kernel(int M, int Ncols, int Kdim,
                        const float* __restrict__ A, int lda,
                        const float* __restrict__ B, int ldb,
                        float* __restrict__ C, int ldc, float alpha)
{
    __shared__ float As[2][8][128];
    __shared__ float Bs[2][8][128];
    const int tid = threadIdx.x;
    const int m0 = blockIdx.y * 128;
    const int n0 = blockIdx.x * 128;
    const int arow = tid >> 1;
    const int acol = (tid & 1) << 2;
    const int brow = tid >> 5;
    const int bcol = (tid & 31) << 2;
    const float* Ap = A + (size_t)(m0 + arow) * lda + acol;
    const float* Bp = B + (size_t)brow * ldb + n0 + bcol;
    const int tx = tid & 15, ty = tid >> 4;

    float acc[8][8];
#pragma unroll
    for (int i = 0; i < 8; i++)
#pragma unroll
        for (int j = 0; j < 8; j++) acc[i][j] = 0.f;

    float4 a4 = *(const float4*)Ap;
    float4 b4 = *(const float4*)Bp;
    As[0][acol+0][arow] = a4.x; As[0][acol+1][arow] = a4.y;
    As[0][acol+2][arow] = a4.z; As[0][acol+3][arow] = a4.w;
    *(float4*)(&Bs[0][brow][bcol]) = b4;
    __syncthreads();

    const int ntiles = Kdim >> 3;
    for (int it = 0; it < ntiles; ++it) {
        const int buf = it & 1;
        if (it + 1 < ntiles) {
            const int k0 = (it + 1) << 3;
            a4 = *(const float4*)(Ap + k0);
            b4 = *(const float4*)(Bp + (size_t)k0 * ldb);
        }
#pragma unroll
        for (int kk = 0; kk < 8; ++kk) {
            float ar[8], br[8];
            *(float4*)&ar[0] = *(const float4*)&As[buf][kk][ty*8];
            *(float4*)&ar[4] = *(const float4*)&As[buf][kk][ty*8+4];
            *(float4*)&br[0] = *(const float4*)&Bs[buf][kk][tx*8];
            *(float4*)&br[4] = *(const float4*)&Bs[buf][kk][tx*8+4];
#pragma unroll
            for (int i = 0; i < 8; i++)
#pragma unroll
                for (int j = 0; j < 8; j++)
                    acc[i][j] = fmaf(ar[i], br[j], acc[i][j]);
        }
        if (it + 1 < ntiles) {
            const int nb = buf ^ 1;
            As[nb][acol+0][arow] = a4.x; As[nb][acol+1][arow] = a4.y;
            As[nb][acol+2][arow] = a4.z; As[nb][acol+3][arow] = a4.w;
            *(float4*)(&Bs[nb][brow][bcol]) = b4;
            __syncthreads();
        }
    }
#pragma unroll
    for (int i = 0; i < 8; i++) {
        float* Cp = C + (size_t)(m0 + ty*8 + i) * ldc + n0 + tx*8;
        float4 v0 = make_float4(alpha*acc[i][0], alpha*acc[i][1], alpha*acc[i][2], alpha*acc[i][3]);
        float4 v1 = make_float4(alpha*acc[i][4], alpha*acc[i][5], alpha*acc[i][6], alpha*acc[i][7]);
        *(float4*)Cp = v0; *(float4*)(Cp + 4) = v1;
    }
}

// ---------------- Multi-term weight GEMM with fused epilogue ----------------
// C(NB, O) = bias + X(NB,Fp)@W[0] + sum_{t=1..4} Yslice_t(NB,Fp)@W[t]
// mode 0: gate  -> g-style: gateOut[row*256+col] = sigmoid(v)       (O=256)
// mode 1: cand  -> state[row*128+col] = u*s + (1-u)*tanh(v)          (O=128)
__global__ __launch_bounds__(256)
void sgemm_weight_kernel(int O, int Fp,
                         const float* __restrict__ X,
                         const float* __restrict__ Yb,
                         const float* __restrict__ W,
                         const float* __restrict__ bias,
                         float* __restrict__ gateOut,
                         const float* __restrict__ gateIn,
                         float* __restrict__ state,
                         int mode)
{
    __shared__ float As[2][8][128];
    __shared__ float Bs[2][8][128];
    const int tid = threadIdx.x;
    const int m0 = blockIdx.y * 128;
    const int n0 = blockIdx.x * 128;
    const int arow = tid >> 1;
    const int acol = (tid & 1) << 2;
    const int brow = tid >> 5;
    const int bcol = (tid & 31) << 2;
    const int tx = tid & 15, ty = tid >> 4;
    const int tilesPerTerm = Fp >> 3;
    const int ntiles = 5 * tilesPerTerm;
    const size_t termStride = (size_t)NB * Fp;

    float acc[8][8];
#pragma unroll
    for (int i = 0; i < 8; i++)
#pragma unroll
        for (int j = 0; j < 8; j++) acc[i][j] = 0.f;

    // prologue: tile 0 (term 0, k0 = 0)
    float4 a4 = *(const float4*)(X + (size_t)(m0 + arow) * Fp + acol);
    float4 b4 = *(const float4*)(W + (size_t)brow * O + n0 + bcol);
    As[0][acol+0][arow] = a4.x; As[0][acol+1][arow] = a4.y;
    As[0][acol+2][arow] = a4.z; As[0][acol+3][arow] = a4.w;
    *(float4*)(&Bs[0][brow][bcol]) = b4;
    __syncthreads();

    for (int tt = 0; tt < ntiles; ++tt) {
        const int buf = tt & 1;
        if (tt + 1 < ntiles) {
            const int t2 = tt + 1;
            const int term = t2 / tilesPerTerm;
            const int k0 = (t2 - term * tilesPerTerm) << 3;
            const float* Ap = (term == 0) ? X : (Yb + (size_t)(term - 1) * termStride);
            a4 = *(const float4*)(Ap + (size_t)(m0 + arow) * Fp + k0 + acol);
            b4 = *(const float4*)(W + ((size_t)term * Fp + k0 + brow) * O + n0 + bcol);
        }
#pragma unroll
        for (int kk = 0; kk < 8; ++kk) {
            float ar[8], br[8];
            *(float4*)&ar[0] = *(const float4*)&As[buf][kk][ty*8];
            *(float4*)&ar[4] = *(const float4*)&As[buf][kk][ty*8+4];
            *(float4*)&br[0] = *(const float4*)&Bs[buf][kk][tx*8];
            *(float4*)&br[4] = *(const float4*)&Bs[buf][kk][tx*8+4];
#pragma unroll
            for (int i = 0; i < 8; i++)
#pragma unroll
                for (int j = 0; j < 8; j++)
                    acc[i][j] = fmaf(ar[i], br[j], acc[i][j]);
        }
        if (tt + 1 < ntiles) {
            const int nb = buf ^ 1;
            As[nb][acol+0][arow] = a4.x; As[nb][acol+1][arow] = a4.y;
            As[nb][acol+2][arow] = a4.z; As[nb][acol+3][arow] = a4.w;
            *(float4*)(&Bs[nb][brow][bcol]) = b4;
            __syncthreads();
        }
    }

#pragma unroll
    for (int i = 0; i < 8; i++) {
        const int row = m0 + ty*8 + i;
#pragma unroll
        for (int j = 0; j < 8; j++) {
            const int col = n0 + tx*8 + j;
            float v = acc[i][j] + bias[col];
            if (mode == 0) {
                gateOut[(size_t)row * 256 + col] = 1.f / (1.f + expf(-v));
            } else {
                float u = gateIn[(size_t)row * 256 + 128 + col];
                float s = state[(size_t)row * 128 + col];
                state[(size_t)row * 128 + col] = u * s + (1.f - u) * tanhf(v);
            }
        }
    }
}

// ---------------- elementwise helpers ----------------
__global__ void copy_G_kernel(const float* __restrict__ sup)
{
    size_t i = (size_t)blockIdx.x * blockDim.x + threadIdx.x;
    const size_t half = (size_t)NN * NN;
    const size_t total = 2 * half;
    for (; i < total; i += (size_t)gridDim.x * blockDim.x) {
        float v = sup[i];
        size_t dst = (i < half) ? i : i + half;   // A0 -> rows 0..1023, A1 -> rows 2048..3071
        g_G[dst] = v;
    }
}

// dst (5*Fp, O): block0 = W00+W10-W02-W12 ; then W01, W02, W11, W12. Pad rows zero.
__global__ void build_wcat_kernel(float* __restrict__ dst, const float* __restrict__ src,
                                  int F, int Fp, int O, int count)
{
    int idx = blockIdx.x * blockDim.x + threadIdx.x;
    if (idx >= count) return;
    const int blk = idx / (Fp * O);
    const int rem = idx - blk * Fp * O;
    const int f = rem / O;
    const int o = rem - f * O;
    float v = 0.f;
    if (f < F) {
        #define WSK(s,k) src[((((size_t)(s))*3 + (k)) * F + f) * O + o]
        switch (blk) {
            case 0: v = WSK(0,0) + WSK(1,0) - WSK(0,2) - WSK(1,2); break;
            case 1: v = WSK(0,1); break;
            case 2: v = WSK(0,2); break;
            case 3: v = WSK(1,1); break;
            case 4: v = WSK(1,2); break;
        }
        #undef WSK
    }
    dst[idx] = v;
}

// layer0 concat: x[nb, 0:2]=inp, [2:130]= (r*)s0, [130:136]=0   (stride F0P)
__global__ void build_x0_kernel(const float* __restrict__ inp_t,
                                const float* __restrict__ s0,
                                const float* __restrict__ gate, int useReset)
{
    const int nb = blockIdx.x;
    const int c = threadIdx.x;
    if (c >= F0P) return;
    const int n = nb >> 6, b = nb & 63;
    float v;
    if (c < 2) {
        v = inp_t[((size_t)b * NN + n) * 2 + c];
    } else if (c < F0) {
        const int j = c - 2;
        float s = s0[(size_t)nb * HH + j];
        if (useReset) s *= gate[(size_t)nb * 256 + j];
        v = s;
    } else {
        v = 0.f;
    }
    g_x[(size_t)nb * F0P + c] = v;
}

// layer1 concat: x[nb,0:128]=s0_new, [128:256]=(r*)s1   (stride 256)
__global__ void build_x1_kernel(const float* __restrict__ s0,
                                const float* __restrict__ s1,
                                const float* __restrict__ gate, int useReset)
{
    const int nb = blockIdx.x;
    const int c = threadIdx.x;  // 0..127
    g_x[(size_t)nb * F1P + c] = s0[(size_t)nb * HH + c];
    float s = s1[(size_t)nb * HH + c];
    if (useReset) s *= gate[(size_t)nb * 256 + c];
    g_x[(size_t)nb * F1P + 128 + c] = s;
}

// out (2, B, N, H) from states (N, B, H)
__global__ void write_out_kernel(float* __restrict__ out)
{
    const int nb = blockIdx.x;
    const int h = threadIdx.x;  // 0..127
    const int n = nb >> 6, b = nb & 63;
    out[(((size_t)0 * BB + b) * NN + n) * HH + h] = g_s0[(size_t)nb * HH + h];
    out[(((size_t)1 * BB + b) * NN + n) * HH + h] = g_s1[(size_t)nb * HH + h];
}

// ---------------- host orchestration ----------------
extern "C" void kernel_launch(void* const* d_in, const int* in_sizes, int n_in,
                              void* d_out, int out_size)
{
    const float* inputs   = (const float*)d_in[0];
    const float* supports = (const float*)d_in[1];
    const float* ruW0 = (const float*)d_in[2];
    const float* rub0 = (const float*)d_in[3];
    const float* hW0  = (const float*)d_in[4];
    const float* hb0  = (const float*)d_in[5];
    const float* ruW1 = (const float*)d_in[6];
    const float* rub1 = (const float*)d_in[7];
    const float* hW1  = (const float*)d_in[8];
    const float* hb1  = (const float*)d_in[9];
    float* out = (float*)d_out;

    float *G, *X, *Y, *GATE, *S0, *S1, *Wg0, *Wc0, *Wg1, *Wc1;
    cudaGetSymbolAddress((void**)&G,    g_G);
    cudaGetSymbolAddress((void**)&X,    g_x);
    cudaGetSymbolAddress((void**)&Y,    g_y);
    cudaGetSymbolAddress((void**)&GATE, g_gate);
    cudaGetSymbolAddress((void**)&S0,   g_s0);
    cudaGetSymbolAddress((void**)&S1,   g_s1);
    cudaGetSymbolAddress((void**)&Wg0,  g_Wg0);
    cudaGetSymbolAddress((void**)&Wc0,  g_Wc0);
    cudaGetSymbolAddress((void**)&Wg1,  g_Wg1);
    cudaGetSymbolAddress((void**)&Wc1,  g_Wc1);

    // ---- prologue: G = [A0; 2A0^2; A1; 2A1^2], W concatenations, zero states ----
    copy_G_kernel<<<4096, 512>>>(supports);
    sgemm_graph_kernel<<<dim3(8, 8), 256>>>(NN, NN, NN,
        supports, NN, supports, NN, G + (size_t)NN * NN, NN, 2.f);
    sgemm_graph_kernel<<<dim3(8, 8), 256>>>(NN, NN, NN,
        supports + (size_t)NN * NN, NN, supports + (size_t)NN * NN, NN,
        G + (size_t)3 * NN * NN, NN, 2.f);

    int c0 = 5 * F0P * 256; build_wcat_kernel<<<(c0 + 255) / 256, 256>>>(Wg0, ruW0, F0, F0P, 256, c0);
    int c1 = 5 * F0P * 128; build_wcat_kernel<<<(c1 + 255) / 256, 256>>>(Wc0, hW0,  F0, F0P, 128, c1);
    int c2 = 5 * F1P * 256; build_wcat_kernel<<<(c2 + 255) / 256, 256>>>(Wg1, ruW1, F1P, F1P, 256, c2);
    int c3 = 5 * F1P * 128; build_wcat_kernel<<<(c3 + 255) / 256, 256>>>(Wc1, hW1,  F1P, F1P, 128, c3);

    cudaMemsetAsync(S0, 0, (size_t)NB * HH * sizeof(float));
    cudaMemsetAsync(S1, 0, (size_t)NB * HH * sizeof(float));

    // ---- recurrence ----
    for (int t = 0; t < 12; ++t) {
        const float* inp_t = inputs + (size_t)t * BB * NN * 2;

        // ---- layer 0 ----
        build_x0_kernel<<<NB, 160>>>(inp_t, S0, GATE, 0);
        sgemm_graph_kernel<<<dim3(BF0 / 128, 32), 256>>>(4096, BF0, NN, G, NN, X, BF0, Y, BF0, 1.f);
        sgemm_weight_kernel<<<dim3(2, 512), 256>>>(256, F0P, X, Y, Wg0, rub0, GATE, (const float*)0, (float*)0, 0);

        build_x0_kernel<<<NB, 160>>>(inp_t, S0, GATE, 1);
        sgemm_graph_kernel<<<dim3(BF0 / 128, 32), 256>>>(4096, BF0, NN, G, NN, X, BF0, Y, BF0, 1.f);
        sgemm_weight_kernel<<<dim3(1, 512), 256>>>(128, F0P, X, Y, Wc0, hb0, (float*)0, GATE, S0, 1);

        // ---- layer 1 ----
        build_x1_kernel<<<NB, 128>>>(S0, S1, GATE, 0);
        sgemm_graph_kernel<<<dim3(BF1 / 128, 32), 256>>>(4096, BF1, NN, G, NN, X, BF1, Y, BF1, 1.f);
        sgemm_weight_kernel<<<dim3(2, 512), 256>>>(256, F1P, X, Y, Wg1, rub1, GATE, (const float*)0, (float*)0, 0);

        build_x1_kernel<<<NB, 128>>>(S0, S1, GATE, 1);
        sgemm_graph_kernel<<<dim3(BF1 / 128, 32), 256>>>(4096, BF1, NN, G, NN, X, BF1, Y, BF1, 1.f);
        sgemm_weight_kernel<<<dim3(1, 512), 256>>>(128, F1P, X, Y, Wc1, hb1, (float*)0, GATE, S1, 1);
    }

    write_out_kernel<<<NB, 128>>>(out);
}